// round 3
// baseline (speedup 1.0000x reference)
#include <cuda_runtime.h>
#include <math.h>
#include <float.h>
#include <limits.h>

#define BB 4
#define NN 2048
#define DD 1024
#define EE 8
#define BT 128
#define BE 32
#define BN 8192
#define BND_ELEMS 8388608
#define SCALE_ATT 0.08838834764831845f   // 1/sqrt(128)

#define PAD 132              // GEMM smem row pad (mult of 4 -> aligned float4 rows)
#define PQ 68                // attn transposed-tile row pad (mult of 4)
#define DQKV_SMEM ((16*PAD + 16*PAD + 128*PAD)*4)
#define ATTN_SMEM ((128*PQ*2 + 64*PAD + 64*PQ)*4 + 64*4*3)

// ---------------- scratch (static device globals) ----------------
__device__ float d_probs[BN*EE];
__device__ int   d_e1[BN];
__device__ int   d_e2[BN];
__device__ float d_w1t[BN];
__device__ float d_w2t[BN];
__device__ int   d_cnt[BE];
__device__ int   d_idxg[BE*NN];
__device__ float d_wgtg[BE*NN];
__device__ int   d_posg[BE*NN];
__device__ float d_qb[(size_t)BE*NN*BT];
__device__ float d_kb[(size_t)BE*NN*BT];
__device__ float d_vb[(size_t)BE*NN*BT];
__device__ float d_ob[(size_t)BE*NN*BT];

// active_mask dtype sniffing: u8 / i32 / f32 encodings of a bool mask.
__device__ __forceinline__ int mask_mode(const unsigned char* act) {
    if (act[2] == 0x80 && act[3] == 0x3F) return 2;                         // float32 1.0f
    if (act[0] != 0 && act[1] == 0 && act[2] == 0 && act[3] == 0) return 1; // int32 1
    return 0;                                                               // uint8
}
__device__ __forceinline__ int is_active(const unsigned char* act, int mode, int t) {
    if (mode == 2) return ((const float*)act)[t] != 0.f;
    if (mode == 1) return ((const int*)act)[t] != 0;
    return act[t] != 0;
}

__device__ __forceinline__ void fma_8x8(float acc[8][8], float4 a0, float4 a1,
                                        float4 b0, float4 b1) {
    float av[8] = {a0.x,a0.y,a0.z,a0.w,a1.x,a1.y,a1.z,a1.w};
    float bv[8] = {b0.x,b0.y,b0.z,b0.w,b1.x,b1.y,b1.z,b1.w};
    #pragma unroll
    for (int i = 0; i < 8; i++)
        #pragma unroll
        for (int j = 0; j < 8; j++) acc[i][j] = fmaf(av[i], bv[j], acc[i][j]);
}

// ---------------- 1) router: warp per token ----------------
__global__ void router_kernel(const float* __restrict__ x, const float* __restrict__ Wg) {
    __shared__ float sW[EE][DD];
    const int tid = threadIdx.x;
    for (int i = tid; i < DD*EE; i += 256) {
        int d = i >> 3, e = i & 7;
        sW[e][d] = Wg[i];
    }
    __syncthreads();
    const int wid = tid >> 5, lane = tid & 31;
    const int t = blockIdx.x * 8 + wid;
    float acc[EE];
    #pragma unroll
    for (int e = 0; e < EE; e++) acc[e] = 0.f;
    const float* xr = x + (size_t)t * DD;
    for (int k = 0; k < DD/32; k++) {
        float xv = xr[lane + k*32];
        #pragma unroll
        for (int e = 0; e < EE; e++) acc[e] += xv * sW[e][lane + k*32];
    }
    #pragma unroll
    for (int e = 0; e < EE; e++) {
        #pragma unroll
        for (int o = 16; o; o >>= 1) acc[e] += __shfl_down_sync(0xffffffffu, acc[e], o);
    }
    if (lane == 0) {
        float m = acc[0];
        #pragma unroll
        for (int e = 1; e < EE; e++) m = fmaxf(m, acc[e]);
        float p[EE]; float s = 0.f;
        #pragma unroll
        for (int e = 0; e < EE; e++) { p[e] = expf(acc[e] - m); s += p[e]; }
        float inv = 1.f / s;
        #pragma unroll
        for (int e = 0; e < EE; e++) { p[e] *= inv; d_probs[t*EE + e] = p[e]; }
        int i1 = 0; float p1 = p[0];
        #pragma unroll
        for (int e = 1; e < EE; e++) if (p[e] > p1) { p1 = p[e]; i1 = e; }
        int i2 = -1; float p2 = -FLT_MAX;
        #pragma unroll
        for (int e = 0; e < EE; e++) if (e != i1 && p[e] > p2) { p2 = p[e]; i2 = e; }
        float den = p1 + p2;
        d_e1[t] = i1; d_e2[t] = i2;
        d_w1t[t] = p1 / den; d_w2t[t] = p2 / den;
    }
}

// ---------------- 2) deterministic compaction (ballot scan) ----------------
__global__ void compact_kernel(const int* __restrict__ pos, const unsigned char* __restrict__ act) {
    const int be = blockIdx.x, b = be >> 3, e = be & 7;
    const int tid = threadIdx.x, w = tid >> 5, lane = tid & 31;
    const int mm2 = mask_mode(act);
    __shared__ int wtot[8];
    int base = 0;
    for (int t0 = 0; t0 < NN; t0 += 256) {
        int t = t0 + tid, gt = b*NN + t;
        int f = is_active(act, mm2, gt) && (d_e1[gt] == e || d_e2[gt] == e);
        unsigned bal = __ballot_sync(0xffffffffu, f);
        if (lane == 0) wtot[w] = __popc(bal);
        __syncthreads();
        int wbase = 0, total = 0;
        #pragma unroll
        for (int ww = 0; ww < 8; ww++) {
            int v = wtot[ww];
            if (ww < w) wbase += v;
            total += v;
        }
        if (f) {
            int slot = base + wbase + __popc(bal & ((1u << lane) - 1u));
            d_idxg[be*NN + slot] = t;
            d_wgtg[be*NN + slot] = (d_e1[gt] == e) ? d_w1t[gt] : d_w2t[gt];
            d_posg[be*NN + slot] = pos[gt];
        }
        base += total;
        __syncthreads();
    }
    if (tid == 0) d_cnt[be] = base;
}

// ---------------- 3) fused down-proj + Q/K/V (128x128 tiles, 8x8 micro) ----------------
__global__ __launch_bounds__(256, 2) void dqkv_kernel(
        const float* __restrict__ x, const float* __restrict__ Wd,
        const float* __restrict__ Wq, const float* __restrict__ Wk,
        const float* __restrict__ Wv) {
    const int be = blockIdx.y, b = be >> 3, e = be & 7;
    const int S = d_cnt[be];
    const int m0 = blockIdx.x * 128;
    if (m0 >= S) return;
    extern __shared__ float sm[];
    float* sAT = sm;                 // [16][PAD]  A^T staging (k-major)
    float* sB  = sm + 16*PAD;        // [16][PAD]  B tile (k rows, n cols)
    float* sH  = sB + 16*PAD;        // [128][PAD] h tile (m rows, k cols)
    const int tid = threadIdx.x;
    const int tr = tid >> 4, tc = tid & 15;
    const int ar = tid >> 1, ahk = (tid & 1) * 8;      // A staging: row, k-half
    const int bkr = tid >> 4, bc = (tid & 15) * 8;     // B staging: k row, col

    int gi = m0 + ar; if (gi >= S) gi = S - 1;
    const float* xrow = x + ((size_t)b*NN + d_idxg[be*NN + gi]) * DD;
    const float* We = Wd + (size_t)e * DD * BT;

    float acc[8][8];
    #pragma unroll
    for (int i = 0; i < 8; i++)
        #pragma unroll
        for (int j = 0; j < 8; j++) acc[i][j] = 0.f;

    for (int k0 = 0; k0 < DD; k0 += 16) {
        float4 a0 = *(const float4*)(xrow + k0 + ahk);
        float4 a1 = *(const float4*)(xrow + k0 + ahk + 4);
        sAT[(ahk+0)*PAD + ar] = a0.x;
        sAT[(ahk+1)*PAD + ar] = a0.y;
        sAT[(ahk+2)*PAD + ar] = a0.z;
        sAT[(ahk+3)*PAD + ar] = a0.w;
        sAT[(ahk+4)*PAD + ar] = a1.x;
        sAT[(ahk+5)*PAD + ar] = a1.y;
        sAT[(ahk+6)*PAD + ar] = a1.z;
        sAT[(ahk+7)*PAD + ar] = a1.w;
        const float* bp = We + (size_t)(k0 + bkr) * BT + bc;
        *(float4*)(sB + bkr*PAD + bc)     = *(const float4*)bp;
        *(float4*)(sB + bkr*PAD + bc + 4) = *(const float4*)(bp + 4);
        __syncthreads();
        #pragma unroll
        for (int kk = 0; kk < 16; kk++) {
            float4 qa0 = *(const float4*)(sAT + kk*PAD + tr*8);
            float4 qa1 = *(const float4*)(sAT + kk*PAD + tr*8 + 4);
            float4 vb0 = *(const float4*)(sB + kk*PAD + tc*8);
            float4 vb1 = *(const float4*)(sB + kk*PAD + tc*8 + 4);
            fma_8x8(acc, qa0, qa1, vb0, vb1);
        }
        __syncthreads();
    }
    // stash h tile (row-major, conflict-free float4 stores)
    #pragma unroll
    for (int i = 0; i < 8; i++) {
        *(float4*)(sH + (tr*8+i)*PAD + tc*8)     = make_float4(acc[i][0], acc[i][1], acc[i][2], acc[i][3]);
        *(float4*)(sH + (tr*8+i)*PAD + tc*8 + 4) = make_float4(acc[i][4], acc[i][5], acc[i][6], acc[i][7]);
    }
    __syncthreads();

    const float* Wz[3] = { Wq + (size_t)e*BT*BT, Wk + (size_t)e*BT*BT, Wv + (size_t)e*BT*BT };
    float* Oz[3] = { d_qb + (size_t)be*NN*BT, d_kb + (size_t)be*NN*BT, d_vb + (size_t)be*NN*BT };

    for (int z = 0; z < 3; z++) {
        float a2[8][8];
        #pragma unroll
        for (int i = 0; i < 8; i++)
            #pragma unroll
            for (int j = 0; j < 8; j++) a2[i][j] = 0.f;
        for (int k0 = 0; k0 < BT; k0 += 16) {
            const float* bp = Wz[z] + (size_t)(k0 + bkr) * BT + bc;
            *(float4*)(sB + bkr*PAD + bc)     = *(const float4*)bp;
            *(float4*)(sB + bkr*PAD + bc + 4) = *(const float4*)(bp + 4);
            __syncthreads();
            #pragma unroll
            for (int kk = 0; kk < 16; kk++) {
                float av[8];
                #pragma unroll
                for (int i = 0; i < 8; i++) av[i] = sH[(tr*8+i)*PAD + k0 + kk];
                float4 vb0 = *(const float4*)(sB + kk*PAD + tc*8);
                float4 vb1 = *(const float4*)(sB + kk*PAD + tc*8 + 4);
                float bv[8] = {vb0.x,vb0.y,vb0.z,vb0.w,vb1.x,vb1.y,vb1.z,vb1.w};
                #pragma unroll
                for (int i = 0; i < 8; i++)
                    #pragma unroll
                    for (int j = 0; j < 8; j++) a2[i][j] = fmaf(av[i], bv[j], a2[i][j]);
            }
            __syncthreads();
        }
        float* op = Oz[z];
        #pragma unroll
        for (int i = 0; i < 8; i++) {
            int r = m0 + tr*8 + i;
            if (r < S) {
                *(float4*)(op + (size_t)r*BT + tc*8)     = make_float4(a2[i][0], a2[i][1], a2[i][2], a2[i][3]);
                *(float4*)(op + (size_t)r*BT + tc*8 + 4) = make_float4(a2[i][4], a2[i][5], a2[i][6], a2[i][7]);
            }
        }
    }
}

// ---------------- 4) attention: d-major Q/K tiles, vectorized score + AV ----------------
__global__ __launch_bounds__(256, 1) void attn_kernel() {
    const int be = blockIdx.y;
    const int S = d_cnt[be];
    const int q0 = blockIdx.x * 64;
    if (q0 >= S) return;
    extern __shared__ float sm[];
    float* sQT = sm;                  // [128][PQ]  Q^T (d-major)
    float* sKT = sQT + 128*PQ;        // [128][PQ]  K^T
    float* sV  = sKT + 128*PQ;        // [64][PAD]  V (k rows, d cols)
    float* sPT = sV + 64*PAD;         // [64][PQ]   P^T (k rows, q cols)
    float* sL  = sPT + 64*PQ;         // [64]
    int* sQp = (int*)(sL + 64);
    int* sKp = sQp + 64;
    const int tid = threadIdx.x, tr = tid >> 4, tc = tid & 15;
    const float* gq = d_qb + (size_t)be*NN*BT;
    const float* gk = d_kb + (size_t)be*NN*BT;
    const float* gv = d_vb + (size_t)be*NN*BT;
    const int* gp = d_posg + be*NN;

    // load Q^T: r-major lanes -> conflict-free transpose STS
    for (int idx = tid; idx < 2048; idx += 256) {
        int c4 = (idx >> 6) * 4, r = idx & 63;
        int slot = q0 + r;
        float4 v = make_float4(0.f, 0.f, 0.f, 0.f);
        if (slot < S) v = *(const float4*)(gq + (size_t)slot*BT + c4);
        sQT[(c4+0)*PQ + r] = v.x;
        sQT[(c4+1)*PQ + r] = v.y;
        sQT[(c4+2)*PQ + r] = v.z;
        sQT[(c4+3)*PQ + r] = v.w;
    }
    if (tid < 64) {
        int slot = q0 + tid;
        sQp[tid] = (slot < S) ? gp[slot] : INT_MIN;
        sL[tid] = 0.f;
    }
    float oacc[4][8];
    #pragma unroll
    for (int i = 0; i < 4; i++)
        #pragma unroll
        for (int j = 0; j < 8; j++) oacc[i][j] = 0.f;

    const int kend = min(S, q0 + 64);
    for (int k0 = 0; k0 < kend; k0 += 64) {
        for (int idx = tid; idx < 2048; idx += 256) {
            int c4 = (idx >> 6) * 4, r = idx & 63;
            int slot = k0 + r;
            float4 kv = make_float4(0.f, 0.f, 0.f, 0.f);
            if (slot < S) kv = *(const float4*)(gk + (size_t)slot*BT + c4);
            sKT[(c4+0)*PQ + r] = kv.x;
            sKT[(c4+1)*PQ + r] = kv.y;
            sKT[(c4+2)*PQ + r] = kv.z;
            sKT[(c4+3)*PQ + r] = kv.w;
        }
        for (int idx = tid; idx < 2048; idx += 256) {
            int r = idx >> 5, c4 = (idx & 31) * 4;
            int slot = k0 + r;
            float4 vv = make_float4(0.f, 0.f, 0.f, 0.f);
            if (slot < S) vv = *(const float4*)(gv + (size_t)slot*BT + c4);
            *(float4*)(sV + r*PAD + c4) = vv;
        }
        if (tid < 64) {
            int slot = k0 + tid;
            sKp[tid] = (slot < S) ? gp[slot] : INT_MAX;
        }
        __syncthreads();

        // scores: 64x64 tile, micro 4x4
        float sacc[4][4];
        #pragma unroll
        for (int i = 0; i < 4; i++)
            #pragma unroll
            for (int j = 0; j < 4; j++) sacc[i][j] = 0.f;
        #pragma unroll 4
        for (int d = 0; d < 128; d++) {
            float4 qa = *(const float4*)(sQT + d*PQ + tr*4);
            float4 kb = *(const float4*)(sKT + d*PQ + tc*4);
            float av[4] = {qa.x, qa.y, qa.z, qa.w};
            float bv[4] = {kb.x, kb.y, kb.z, kb.w};
            #pragma unroll
            for (int i = 0; i < 4; i++)
                #pragma unroll
                for (int j = 0; j < 4; j++) sacc[i][j] = fmaf(av[i], bv[j], sacc[i][j]);
        }
        float lp[4];
        #pragma unroll
        for (int i = 0; i < 4; i++) {
            int qp = sQp[tr*4 + i];
            lp[i] = 0.f;
            #pragma unroll
            for (int j = 0; j < 4; j++) {
                int kc = tc*4 + j;
                float pv = (qp >= sKp[kc]) ? __expf(sacc[i][j] * SCALE_ATT) : 0.f;
                sPT[kc*PQ + tr*4 + i] = pv;
                lp[i] += pv;
            }
        }
        #pragma unroll
        for (int i = 0; i < 4; i++) {
            #pragma unroll
            for (int o = 8; o; o >>= 1) lp[i] += __shfl_down_sync(0xffffffffu, lp[i], o, 16);
        }
        if (tc == 0) {
            #pragma unroll
            for (int i = 0; i < 4; i++) sL[tr*4 + i] += lp[i];
        }
        __syncthreads();

        // AV: 64q x 128d, micro 4x8
        #pragma unroll 2
        for (int kk = 0; kk < 64; kk++) {
            float4 pa = *(const float4*)(sPT + kk*PQ + tr*4);
            float4 v0 = *(const float4*)(sV + kk*PAD + tc*8);
            float4 v1 = *(const float4*)(sV + kk*PAD + tc*8 + 4);
            float pv[4] = {pa.x, pa.y, pa.z, pa.w};
            float vv[8] = {v0.x,v0.y,v0.z,v0.w,v1.x,v1.y,v1.z,v1.w};
            #pragma unroll
            for (int i = 0; i < 4; i++)
                #pragma unroll
                for (int j = 0; j < 8; j++) oacc[i][j] = fmaf(pv[i], vv[j], oacc[i][j]);
        }
        __syncthreads();
    }
    float* go = d_ob + (size_t)be*NN*BT;
    #pragma unroll
    for (int i = 0; i < 4; i++) {
        int slot = q0 + tr*4 + i;
        if (slot < S) {
            float inv = 1.f / sL[tr*4 + i];
            *(float4*)(go + (size_t)slot*BT + tc*8) =
                make_float4(oacc[i][0]*inv, oacc[i][1]*inv, oacc[i][2]*inv, oacc[i][3]*inv);
            *(float4*)(go + (size_t)slot*BT + tc*8 + 4) =
                make_float4(oacc[i][4]*inv, oacc[i][5]*inv, oacc[i][6]*inv, oacc[i][7]*inv);
        }
    }
}

// ---------------- 5) up-proj + weighted combine ----------------
__global__ __launch_bounds__(256, 2) void up_kernel(const float* __restrict__ Wu,
                                                    float* __restrict__ out) {
    const int be = blockIdx.z, b = be >> 3, e = be & 7;
    const int S = d_cnt[be];
    const int m0 = blockIdx.x * 128;
    if (m0 >= S) return;
    const int n0 = blockIdx.y * 128;
    __shared__ float sAT[16*PAD];
    __shared__ float sB[16*PAD];
    const int tid = threadIdx.x;
    const int tr = tid >> 4, tc = tid & 15;
    const int ar = tid >> 1, ahk = (tid & 1) * 8;
    const int bkr = tid >> 4, bc = (tid & 15) * 8;
    int gi = m0 + ar; if (gi >= S) gi = S - 1;
    const float* Arow = d_ob + (size_t)be*NN*BT + (size_t)gi*BT;
    const float* We = Wu + (size_t)e * BT * DD;
    float acc[8][8];
    #pragma unroll
    for (int i = 0; i < 8; i++)
        #pragma unroll
        for (int j = 0; j < 8; j++) acc[i][j] = 0.f;
    for (int k0 = 0; k0 < BT; k0 += 16) {
        float4 a0 = *(const float4*)(Arow + k0 + ahk);
        float4 a1 = *(const float4*)(Arow + k0 + ahk + 4);
        sAT[(ahk+0)*PAD + ar] = a0.x;
        sAT[(ahk+1)*PAD + ar] = a0.y;
        sAT[(ahk+2)*PAD + ar] = a0.z;
        sAT[(ahk+3)*PAD + ar] = a0.w;
        sAT[(ahk+4)*PAD + ar] = a1.x;
        sAT[(ahk+5)*PAD + ar] = a1.y;
        sAT[(ahk+6)*PAD + ar] = a1.z;
        sAT[(ahk+7)*PAD + ar] = a1.w;
        const float* bp = We + (size_t)(k0 + bkr) * DD + n0 + bc;
        *(float4*)(sB + bkr*PAD + bc)     = *(const float4*)bp;
        *(float4*)(sB + bkr*PAD + bc + 4) = *(const float4*)(bp + 4);
        __syncthreads();
        #pragma unroll
        for (int kk = 0; kk < 16; kk++) {
            float4 qa0 = *(const float4*)(sAT + kk*PAD + tr*8);
            float4 qa1 = *(const float4*)(sAT + kk*PAD + tr*8 + 4);
            float4 vb0 = *(const float4*)(sB + kk*PAD + tc*8);
            float4 vb1 = *(const float4*)(sB + kk*PAD + tc*8 + 4);
            fma_8x8(acc, qa0, qa1, vb0, vb1);
        }
        __syncthreads();
    }
    #pragma unroll
    for (int i = 0; i < 8; i++) {
        int r = m0 + tr*8 + i;
        if (r < S) {
            int tok = d_idxg[be*NN + r];
            float w = d_wgtg[be*NN + r];
            float* orow = out + ((size_t)b*NN + tok)*DD + n0 + tc*8;
            #pragma unroll
            for (int j = 0; j < 8; j++) atomicAdd(orow + j, acc[i][j] * w);
        }
    }
}

// ---------------- 6) deterministic loss / max-violation ----------------
__global__ void finalize_kernel(const unsigned char* __restrict__ act, float* __restrict__ out,
                                int out_size) {
    __shared__ float sp[256*EE];
    __shared__ float sc2[256*EE];
    __shared__ float sa[256];
    const int tid = threadIdx.x;
    const int mm2 = mask_mode(act);
    float p[EE], c[EE];
    #pragma unroll
    for (int e = 0; e < EE; e++) { p[e] = 0.f; c[e] = 0.f; }
    float a = 0.f;
    for (int t = tid; t < BN; t += 256) {
        if (is_active(act, mm2, t)) {
            a += 1.f;
            #pragma unroll
            for (int e = 0; e < EE; e++) p[e] += d_probs[t*EE + e];
            c[d_e1[t]] += 1.f;
            c[d_e2[t]] += 1.f;
        }
    }
    #pragma unroll
    for (int e = 0; e < EE; e++) { sp[tid*EE + e] = p[e]; sc2[tid*EE + e] = c[e]; }
    sa[tid] = a;
    __syncthreads();
    for (int s = 128; s; s >>= 1) {
        if (tid < s) {
            #pragma unroll
            for (int e = 0; e < EE; e++) {
                sp[tid*EE + e] += sp[(tid + s)*EE + e];
                sc2[tid*EE + e] += sc2[(tid + s)*EE + e];
            }
            sa[tid] += sa[tid + s];
        }
        __syncthreads();
    }
    if (tid == 0) {
        float denom = fmaxf(sa[0], 1.f);
        float loss = 0.f, fm = 0.f;
        #pragma unroll
        for (int e = 0; e < EE; e++) {
            float frac = sc2[e] / denom;
            float pm = sp[e] / denom;
            loss += frac * pm;
            fm = fmaxf(fm, frac);
        }
        if (out_size >= BND_ELEMS + 2) {
            out[BND_ELEMS]     = 4.f * loss;
            out[BND_ELEMS + 1] = fm * 4.f - 1.f;
        }
    }
}

// ---------------- launch ----------------
extern "C" void kernel_launch(void* const* d_in, const int* in_sizes, int n_in,
                              void* d_out, int out_size) {
    (void)in_sizes; (void)n_in;
    const float* x  = (const float*)d_in[0];
    const int* pos  = (const int*)d_in[1];
    const unsigned char* act = (const unsigned char*)d_in[2];
    const float* Wg = (const float*)d_in[3];
    const float* Wd = (const float*)d_in[4];
    const float* Wq = (const float*)d_in[5];
    const float* Wk = (const float*)d_in[6];
    const float* Wv = (const float*)d_in[7];
    const float* Wu = (const float*)d_in[8];
    float* out = (float*)d_out;

    cudaFuncSetAttribute(dqkv_kernel, cudaFuncAttributeMaxDynamicSharedMemorySize, DQKV_SMEM);
    cudaFuncSetAttribute(attn_kernel, cudaFuncAttributeMaxDynamicSharedMemorySize, ATTN_SMEM);

    cudaMemsetAsync(out, 0, (size_t)BND_ELEMS * sizeof(float), 0);
    router_kernel<<<BN/8, 256>>>(x, Wg);
    compact_kernel<<<BE, 256>>>(pos, act);
    dqkv_kernel<<<dim3(NN/128, BE), 256, DQKV_SMEM>>>(x, Wd, Wq, Wk, Wv);
    attn_kernel<<<dim3(NN/64, BE), 256, ATTN_SMEM>>>();
    up_kernel<<<dim3(NN/128, DD/128, BE), 256>>>(Wu, out);
    finalize_kernel<<<1, 256>>>(act, out, out_size);
}

// round 4
// speedup vs baseline: 1.0217x; 1.0217x over previous
#include <cuda_runtime.h>
#include <math.h>
#include <float.h>
#include <limits.h>

#define BB 4
#define NN 2048
#define DD 1024
#define EE 8
#define BT 128
#define BE 32
#define BN 8192
#define BND_ELEMS 8388608
#define SCALE_ATT 0.08838834764831845f   // 1/sqrt(128)

#define PAD 132              // GEMM smem row pad (mult of 4 -> aligned float4 rows)
#define PQ 68                // attn transposed-tile row pad (mult of 4)
#define DQKV_SMEM ((16*PAD + 16*PAD + 128*PAD)*4)
// attn smem: QT[128][PQ] + KT[128][PQ] (P^T aliases KT's first 64*PQ) + V[64][128] + L[64] + Qp/Kp
#define ATTN_SMEM ((128*PQ*2 + 64*128 + 64)*4 + 64*4*2)

// ---------------- scratch (static device globals) ----------------
__device__ float d_probs[BN*EE];
__device__ int   d_e1[BN];
__device__ int   d_e2[BN];
__device__ float d_w1t[BN];
__device__ float d_w2t[BN];
__device__ int   d_cnt[BE];
__device__ int   d_idxg[BE*NN];
__device__ float d_wgtg[BE*NN];
__device__ int   d_posg[BE*NN];
__device__ float d_qb[(size_t)BE*NN*BT];
__device__ float d_kb[(size_t)BE*NN*BT];
__device__ float d_vb[(size_t)BE*NN*BT];
__device__ float d_ob[(size_t)BE*NN*BT];

// active_mask dtype sniffing: u8 / i32 / f32 encodings of a bool mask.
__device__ __forceinline__ int mask_mode(const unsigned char* act) {
    if (act[2] == 0x80 && act[3] == 0x3F) return 2;                         // float32 1.0f
    if (act[0] != 0 && act[1] == 0 && act[2] == 0 && act[3] == 0) return 1; // int32 1
    return 0;                                                               // uint8
}
__device__ __forceinline__ int is_active(const unsigned char* act, int mode, int t) {
    if (mode == 2) return ((const float*)act)[t] != 0.f;
    if (mode == 1) return ((const int*)act)[t] != 0;
    return act[t] != 0;
}

__device__ __forceinline__ void fma_8x8(float acc[8][8], float4 a0, float4 a1,
                                        float4 b0, float4 b1) {
    float av[8] = {a0.x,a0.y,a0.z,a0.w,a1.x,a1.y,a1.z,a1.w};
    float bv[8] = {b0.x,b0.y,b0.z,b0.w,b1.x,b1.y,b1.z,b1.w};
    #pragma unroll
    for (int i = 0; i < 8; i++)
        #pragma unroll
        for (int j = 0; j < 8; j++) acc[i][j] = fmaf(av[i], bv[j], acc[i][j]);
}

// ---------------- 1) router: warp per token ----------------
__global__ void router_kernel(const float* __restrict__ x, const float* __restrict__ Wg) {
    __shared__ float sW[EE][DD];
    const int tid = threadIdx.x;
    for (int i = tid; i < DD*EE; i += 256) {
        int d = i >> 3, e = i & 7;
        sW[e][d] = Wg[i];
    }
    __syncthreads();
    const int wid = tid >> 5, lane = tid & 31;
    const int t = blockIdx.x * 8 + wid;
    float acc[EE];
    #pragma unroll
    for (int e = 0; e < EE; e++) acc[e] = 0.f;
    const float* xr = x + (size_t)t * DD;
    for (int k = 0; k < DD/32; k++) {
        float xv = xr[lane + k*32];
        #pragma unroll
        for (int e = 0; e < EE; e++) acc[e] += xv * sW[e][lane + k*32];
    }
    #pragma unroll
    for (int e = 0; e < EE; e++) {
        #pragma unroll
        for (int o = 16; o; o >>= 1) acc[e] += __shfl_down_sync(0xffffffffu, acc[e], o);
    }
    if (lane == 0) {
        float m = acc[0];
        #pragma unroll
        for (int e = 1; e < EE; e++) m = fmaxf(m, acc[e]);
        float p[EE]; float s = 0.f;
        #pragma unroll
        for (int e = 0; e < EE; e++) { p[e] = expf(acc[e] - m); s += p[e]; }
        float inv = 1.f / s;
        #pragma unroll
        for (int e = 0; e < EE; e++) { p[e] *= inv; d_probs[t*EE + e] = p[e]; }
        int i1 = 0; float p1 = p[0];
        #pragma unroll
        for (int e = 1; e < EE; e++) if (p[e] > p1) { p1 = p[e]; i1 = e; }
        int i2 = -1; float p2 = -FLT_MAX;
        #pragma unroll
        for (int e = 0; e < EE; e++) if (e != i1 && p[e] > p2) { p2 = p[e]; i2 = e; }
        float den = p1 + p2;
        d_e1[t] = i1; d_e2[t] = i2;
        d_w1t[t] = p1 / den; d_w2t[t] = p2 / den;
    }
}

// ---------------- 2) deterministic compaction (ballot scan) ----------------
__global__ void compact_kernel(const int* __restrict__ pos, const unsigned char* __restrict__ act) {
    const int be = blockIdx.x, b = be >> 3, e = be & 7;
    const int tid = threadIdx.x, w = tid >> 5, lane = tid & 31;
    const int mm2 = mask_mode(act);
    __shared__ int wtot[8];
    int base = 0;
    for (int t0 = 0; t0 < NN; t0 += 256) {
        int t = t0 + tid, gt = b*NN + t;
        int f = is_active(act, mm2, gt) && (d_e1[gt] == e || d_e2[gt] == e);
        unsigned bal = __ballot_sync(0xffffffffu, f);
        if (lane == 0) wtot[w] = __popc(bal);
        __syncthreads();
        int wbase = 0, total = 0;
        #pragma unroll
        for (int ww = 0; ww < 8; ww++) {
            int v = wtot[ww];
            if (ww < w) wbase += v;
            total += v;
        }
        if (f) {
            int slot = base + wbase + __popc(bal & ((1u << lane) - 1u));
            d_idxg[be*NN + slot] = t;
            d_wgtg[be*NN + slot] = (d_e1[gt] == e) ? d_w1t[gt] : d_w2t[gt];
            d_posg[be*NN + slot] = pos[gt];
        }
        base += total;
        __syncthreads();
    }
    if (tid == 0) d_cnt[be] = base;
}

// ---------------- 3) fused down-proj + Q/K/V (128x128 tiles, 8x8 micro) ----------------
__global__ __launch_bounds__(256, 2) void dqkv_kernel(
        const float* __restrict__ x, const float* __restrict__ Wd,
        const float* __restrict__ Wq, const float* __restrict__ Wk,
        const float* __restrict__ Wv) {
    const int be = blockIdx.y, b = be >> 3, e = be & 7;
    const int S = d_cnt[be];
    const int m0 = blockIdx.x * 128;
    if (m0 >= S) return;
    extern __shared__ float sm[];
    float* sAT = sm;                 // [16][PAD]  A^T staging (k-major)
    float* sB  = sm + 16*PAD;        // [16][PAD]  B tile (k rows, n cols)
    float* sH  = sB + 16*PAD;        // [128][PAD] h tile (m rows, k cols)
    const int tid = threadIdx.x;
    const int tr = tid >> 4, tc = tid & 15;
    const int ar = tid >> 1, ahk = (tid & 1) * 8;      // A staging: row, k-half
    const int bkr = tid >> 4, bc = (tid & 15) * 8;     // B staging: k row, col

    int gi = m0 + ar; if (gi >= S) gi = S - 1;
    const float* xrow = x + ((size_t)b*NN + d_idxg[be*NN + gi]) * DD;
    const float* We = Wd + (size_t)e * DD * BT;

    float acc[8][8];
    #pragma unroll
    for (int i = 0; i < 8; i++)
        #pragma unroll
        for (int j = 0; j < 8; j++) acc[i][j] = 0.f;

    for (int k0 = 0; k0 < DD; k0 += 16) {
        float4 a0 = *(const float4*)(xrow + k0 + ahk);
        float4 a1 = *(const float4*)(xrow + k0 + ahk + 4);
        sAT[(ahk+0)*PAD + ar] = a0.x;
        sAT[(ahk+1)*PAD + ar] = a0.y;
        sAT[(ahk+2)*PAD + ar] = a0.z;
        sAT[(ahk+3)*PAD + ar] = a0.w;
        sAT[(ahk+4)*PAD + ar] = a1.x;
        sAT[(ahk+5)*PAD + ar] = a1.y;
        sAT[(ahk+6)*PAD + ar] = a1.z;
        sAT[(ahk+7)*PAD + ar] = a1.w;
        const float* bp = We + (size_t)(k0 + bkr) * BT + bc;
        *(float4*)(sB + bkr*PAD + bc)     = *(const float4*)bp;
        *(float4*)(sB + bkr*PAD + bc + 4) = *(const float4*)(bp + 4);
        __syncthreads();
        #pragma unroll
        for (int kk = 0; kk < 16; kk++) {
            float4 qa0 = *(const float4*)(sAT + kk*PAD + tr*8);
            float4 qa1 = *(const float4*)(sAT + kk*PAD + tr*8 + 4);
            float4 vb0 = *(const float4*)(sB + kk*PAD + tc*8);
            float4 vb1 = *(const float4*)(sB + kk*PAD + tc*8 + 4);
            fma_8x8(acc, qa0, qa1, vb0, vb1);
        }
        __syncthreads();
    }
    // stash h tile (row-major, conflict-free float4 stores)
    #pragma unroll
    for (int i = 0; i < 8; i++) {
        *(float4*)(sH + (tr*8+i)*PAD + tc*8)     = make_float4(acc[i][0], acc[i][1], acc[i][2], acc[i][3]);
        *(float4*)(sH + (tr*8+i)*PAD + tc*8 + 4) = make_float4(acc[i][4], acc[i][5], acc[i][6], acc[i][7]);
    }
    __syncthreads();

    const float* Wz[3] = { Wq + (size_t)e*BT*BT, Wk + (size_t)e*BT*BT, Wv + (size_t)e*BT*BT };
    float* Oz[3] = { d_qb + (size_t)be*NN*BT, d_kb + (size_t)be*NN*BT, d_vb + (size_t)be*NN*BT };

    for (int z = 0; z < 3; z++) {
        float a2[8][8];
        #pragma unroll
        for (int i = 0; i < 8; i++)
            #pragma unroll
            for (int j = 0; j < 8; j++) a2[i][j] = 0.f;
        for (int k0 = 0; k0 < BT; k0 += 16) {
            const float* bp = Wz[z] + (size_t)(k0 + bkr) * BT + bc;
            *(float4*)(sB + bkr*PAD + bc)     = *(const float4*)bp;
            *(float4*)(sB + bkr*PAD + bc + 4) = *(const float4*)(bp + 4);
            __syncthreads();
            #pragma unroll
            for (int kk = 0; kk < 16; kk++) {
                float av[8];
                #pragma unroll
                for (int i = 0; i < 8; i++) av[i] = sH[(tr*8+i)*PAD + k0 + kk];
                float4 vb0 = *(const float4*)(sB + kk*PAD + tc*8);
                float4 vb1 = *(const float4*)(sB + kk*PAD + tc*8 + 4);
                float bv[8] = {vb0.x,vb0.y,vb0.z,vb0.w,vb1.x,vb1.y,vb1.z,vb1.w};
                #pragma unroll
                for (int i = 0; i < 8; i++)
                    #pragma unroll
                    for (int j = 0; j < 8; j++) a2[i][j] = fmaf(av[i], bv[j], a2[i][j]);
            }
            __syncthreads();
        }
        float* op = Oz[z];
        #pragma unroll
        for (int i = 0; i < 8; i++) {
            int r = m0 + tr*8 + i;
            if (r < S) {
                *(float4*)(op + (size_t)r*BT + tc*8)     = make_float4(a2[i][0], a2[i][1], a2[i][2], a2[i][3]);
                *(float4*)(op + (size_t)r*BT + tc*8 + 4) = make_float4(a2[i][4], a2[i][5], a2[i][6], a2[i][7]);
            }
        }
    }
}

// ---------------- 4) attention: d-major Q/K tiles, P^T aliased into K^T region ----------------
__global__ __launch_bounds__(256, 2) void attn_kernel() {
    const int be = blockIdx.y;
    const int S = d_cnt[be];
    const int q0 = blockIdx.x * 64;
    if (q0 >= S) return;
    extern __shared__ float sm[];
    float* sQT = sm;                  // [128][PQ]  Q^T (d-major)
    float* sKT = sQT + 128*PQ;        // [128][PQ]  K^T  (first 64*PQ reused as P^T)
    float* sPT = sKT;                 // alias: P^T (k rows, q cols)
    float* sV  = sKT + 128*PQ;        // [64][128]  V (k rows, d cols)
    float* sL  = sV + 64*128;         // [64]
    int* sQp = (int*)(sL + 64);
    int* sKp = sQp + 64;
    const int tid = threadIdx.x, tr = tid >> 4, tc = tid & 15;
    const float* gq = d_qb + (size_t)be*NN*BT;
    const float* gk = d_kb + (size_t)be*NN*BT;
    const float* gv = d_vb + (size_t)be*NN*BT;
    const int* gp = d_posg + be*NN;

    // load Q^T (transpose STS)
    for (int idx = tid; idx < 2048; idx += 256) {
        int c4 = (idx >> 6) * 4, r = idx & 63;
        int slot = q0 + r;
        float4 v = make_float4(0.f, 0.f, 0.f, 0.f);
        if (slot < S) v = *(const float4*)(gq + (size_t)slot*BT + c4);
        sQT[(c4+0)*PQ + r] = v.x;
        sQT[(c4+1)*PQ + r] = v.y;
        sQT[(c4+2)*PQ + r] = v.z;
        sQT[(c4+3)*PQ + r] = v.w;
    }
    if (tid < 64) {
        int slot = q0 + tid;
        sQp[tid] = (slot < S) ? gp[slot] : INT_MIN;
        sL[tid] = 0.f;
    }
    float oacc[4][8];
    #pragma unroll
    for (int i = 0; i < 4; i++)
        #pragma unroll
        for (int j = 0; j < 8; j++) oacc[i][j] = 0.f;

    const int kend = min(S, q0 + 64);
    for (int k0 = 0; k0 < kend; k0 += 64) {
        for (int idx = tid; idx < 2048; idx += 256) {
            int c4 = (idx >> 6) * 4, r = idx & 63;
            int slot = k0 + r;
            float4 kv = make_float4(0.f, 0.f, 0.f, 0.f);
            if (slot < S) kv = *(const float4*)(gk + (size_t)slot*BT + c4);
            sKT[(c4+0)*PQ + r] = kv.x;
            sKT[(c4+1)*PQ + r] = kv.y;
            sKT[(c4+2)*PQ + r] = kv.z;
            sKT[(c4+3)*PQ + r] = kv.w;
        }
        for (int idx = tid; idx < 2048; idx += 256) {
            int r = idx >> 5, c4 = (idx & 31) * 4;
            int slot = k0 + r;
            float4 vv = make_float4(0.f, 0.f, 0.f, 0.f);
            if (slot < S) vv = *(const float4*)(gv + (size_t)slot*BT + c4);
            *(float4*)(sV + r*128 + c4) = vv;
        }
        if (tid < 64) {
            int slot = k0 + tid;
            sKp[tid] = (slot < S) ? gp[slot] : INT_MAX;
        }
        __syncthreads();

        // scores: 64x64 tile, micro 4x4 (reads all of sKT)
        float sacc[4][4];
        #pragma unroll
        for (int i = 0; i < 4; i++)
            #pragma unroll
            for (int j = 0; j < 4; j++) sacc[i][j] = 0.f;
        #pragma unroll 4
        for (int d = 0; d < 128; d++) {
            float4 qa = *(const float4*)(sQT + d*PQ + tr*4);
            float4 kb = *(const float4*)(sKT + d*PQ + tc*4);
            float av[4] = {qa.x, qa.y, qa.z, qa.w};
            float bv[4] = {kb.x, kb.y, kb.z, kb.w};
            #pragma unroll
            for (int i = 0; i < 4; i++)
                #pragma unroll
                for (int j = 0; j < 4; j++) sacc[i][j] = fmaf(av[i], bv[j], sacc[i][j]);
        }
        __syncthreads();   // everyone done reading K before P^T overwrites it

        float lp[4];
        #pragma unroll
        for (int i = 0; i < 4; i++) {
            int qp = sQp[tr*4 + i];
            lp[i] = 0.f;
            #pragma unroll
            for (int j = 0; j < 4; j++) {
                int kc = tc*4 + j;
                float pv = (qp >= sKp[kc]) ? __expf(sacc[i][j] * SCALE_ATT) : 0.f;
                sPT[kc*PQ + tr*4 + i] = pv;
                lp[i] += pv;
            }
        }
        #pragma unroll
        for (int i = 0; i < 4; i++) {
            #pragma unroll
            for (int o = 8; o; o >>= 1) lp[i] += __shfl_down_sync(0xffffffffu, lp[i], o, 16);
        }
        if (tc == 0) {
            #pragma unroll
            for (int i = 0; i < 4; i++) sL[tr*4 + i] += lp[i];
        }
        __syncthreads();

        // AV: 64q x 128d, micro 4x8
        #pragma unroll 2
        for (int kk = 0; kk < 64; kk++) {
            float4 pa = *(const float4*)(sPT + kk*PQ + tr*4);
            float4 v0 = *(const float4*)(sV + kk*128 + tc*8);
            float4 v1 = *(const float4*)(sV + kk*128 + tc*8 + 4);
            float pv[4] = {pa.x, pa.y, pa.z, pa.w};
            float vv[8] = {v0.x,v0.y,v0.z,v0.w,v1.x,v1.y,v1.z,v1.w};
            #pragma unroll
            for (int i = 0; i < 4; i++)
                #pragma unroll
                for (int j = 0; j < 8; j++) oacc[i][j] = fmaf(pv[i], vv[j], oacc[i][j]);
        }
        __syncthreads();
    }
    float* go = d_ob + (size_t)be*NN*BT;
    #pragma unroll
    for (int i = 0; i < 4; i++) {
        int slot = q0 + tr*4 + i;
        if (slot < S) {
            float inv = 1.f / sL[tr*4 + i];
            *(float4*)(go + (size_t)slot*BT + tc*8) =
                make_float4(oacc[i][0]*inv, oacc[i][1]*inv, oacc[i][2]*inv, oacc[i][3]*inv);
            *(float4*)(go + (size_t)slot*BT + tc*8 + 4) =
                make_float4(oacc[i][4]*inv, oacc[i][5]*inv, oacc[i][6]*inv, oacc[i][7]*inv);
        }
    }
}

// ---------------- 5) up-proj + weighted combine ----------------
__global__ __launch_bounds__(256, 2) void up_kernel(const float* __restrict__ Wu,
                                                    float* __restrict__ out) {
    const int be = blockIdx.z, b = be >> 3, e = be & 7;
    const int S = d_cnt[be];
    const int m0 = blockIdx.x * 128;
    if (m0 >= S) return;
    const int n0 = blockIdx.y * 128;
    __shared__ float sAT[16*PAD];
    __shared__ float sB[16*PAD];
    const int tid = threadIdx.x;
    const int tr = tid >> 4, tc = tid & 15;
    const int ar = tid >> 1, ahk = (tid & 1) * 8;
    const int bkr = tid >> 4, bc = (tid & 15) * 8;
    int gi = m0 + ar; if (gi >= S) gi = S - 1;
    const float* Arow = d_ob + (size_t)be*NN*BT + (size_t)gi*BT;
    const float* We = Wu + (size_t)e * BT * DD;
    float acc[8][8];
    #pragma unroll
    for (int i = 0; i < 8; i++)
        #pragma unroll
        for (int j = 0; j < 8; j++) acc[i][j] = 0.f;
    for (int k0 = 0; k0 < BT; k0 += 16) {
        float4 a0 = *(const float4*)(Arow + k0 + ahk);
        float4 a1 = *(const float4*)(Arow + k0 + ahk + 4);
        sAT[(ahk+0)*PAD + ar] = a0.x;
        sAT[(ahk+1)*PAD + ar] = a0.y;
        sAT[(ahk+2)*PAD + ar] = a0.z;
        sAT[(ahk+3)*PAD + ar] = a0.w;
        sAT[(ahk+4)*PAD + ar] = a1.x;
        sAT[(ahk+5)*PAD + ar] = a1.y;
        sAT[(ahk+6)*PAD + ar] = a1.z;
        sAT[(ahk+7)*PAD + ar] = a1.w;
        const float* bp = We + (size_t)(k0 + bkr) * DD + n0 + bc;
        *(float4*)(sB + bkr*PAD + bc)     = *(const float4*)bp;
        *(float4*)(sB + bkr*PAD + bc + 4) = *(const float4*)(bp + 4);
        __syncthreads();
        #pragma unroll
        for (int kk = 0; kk < 16; kk++) {
            float4 qa0 = *(const float4*)(sAT + kk*PAD + tr*8);
            float4 qa1 = *(const float4*)(sAT + kk*PAD + tr*8 + 4);
            float4 vb0 = *(const float4*)(sB + kk*PAD + tc*8);
            float4 vb1 = *(const float4*)(sB + kk*PAD + tc*8 + 4);
            fma_8x8(acc, qa0, qa1, vb0, vb1);
        }
        __syncthreads();
    }
    #pragma unroll
    for (int i = 0; i < 8; i++) {
        int r = m0 + tr*8 + i;
        if (r < S) {
            int tok = d_idxg[be*NN + r];
            float w = d_wgtg[be*NN + r];
            float* orow = out + ((size_t)b*NN + tok)*DD + n0 + tc*8;
            #pragma unroll
            for (int j = 0; j < 8; j++) atomicAdd(orow + j, acc[i][j] * w);
        }
    }
}

// ---------------- 6) deterministic loss / max-violation ----------------
__global__ void finalize_kernel(const unsigned char* __restrict__ act, float* __restrict__ out,
                                int out_size) {
    __shared__ float sp[256*EE];
    __shared__ float sc2[256*EE];
    __shared__ float sa[256];
    const int tid = threadIdx.x;
    const int mm2 = mask_mode(act);
    float p[EE], c[EE];
    #pragma unroll
    for (int e = 0; e < EE; e++) { p[e] = 0.f; c[e] = 0.f; }
    float a = 0.f;
    for (int t = tid; t < BN; t += 256) {
        if (is_active(act, mm2, t)) {
            a += 1.f;
            #pragma unroll
            for (int e = 0; e < EE; e++) p[e] += d_probs[t*EE + e];
            c[d_e1[t]] += 1.f;
            c[d_e2[t]] += 1.f;
        }
    }
    #pragma unroll
    for (int e = 0; e < EE; e++) { sp[tid*EE + e] = p[e]; sc2[tid*EE + e] = c[e]; }
    sa[tid] = a;
    __syncthreads();
    for (int s = 128; s; s >>= 1) {
        if (tid < s) {
            #pragma unroll
            for (int e = 0; e < EE; e++) {
                sp[tid*EE + e] += sp[(tid + s)*EE + e];
                sc2[tid*EE + e] += sc2[(tid + s)*EE + e];
            }
            sa[tid] += sa[tid + s];
        }
        __syncthreads();
    }
    if (tid == 0) {
        float denom = fmaxf(sa[0], 1.f);
        float loss = 0.f, fm = 0.f;
        #pragma unroll
        for (int e = 0; e < EE; e++) {
            float frac = sc2[e] / denom;
            float pm = sp[e] / denom;
            loss += frac * pm;
            fm = fmaxf(fm, frac);
        }
        if (out_size >= BND_ELEMS + 2) {
            out[BND_ELEMS]     = 4.f * loss;
            out[BND_ELEMS + 1] = fm * 4.f - 1.f;
        }
    }
}

// ---------------- launch ----------------
extern "C" void kernel_launch(void* const* d_in, const int* in_sizes, int n_in,
                              void* d_out, int out_size) {
    (void)in_sizes; (void)n_in;
    const float* x  = (const float*)d_in[0];
    const int* pos  = (const int*)d_in[1];
    const unsigned char* act = (const unsigned char*)d_in[2];
    const float* Wg = (const float*)d_in[3];
    const float* Wd = (const float*)d_in[4];
    const float* Wq = (const float*)d_in[5];
    const float* Wk = (const float*)d_in[6];
    const float* Wv = (const float*)d_in[7];
    const float* Wu = (const float*)d_in[8];
    float* out = (float*)d_out;

    cudaFuncSetAttribute(dqkv_kernel, cudaFuncAttributeMaxDynamicSharedMemorySize, DQKV_SMEM);
    cudaFuncSetAttribute(attn_kernel, cudaFuncAttributeMaxDynamicSharedMemorySize, ATTN_SMEM);

    cudaMemsetAsync(out, 0, (size_t)BND_ELEMS * sizeof(float), 0);
    router_kernel<<<BN/8, 256>>>(x, Wg);
    compact_kernel<<<BE, 256>>>(pos, act);
    dqkv_kernel<<<dim3(NN/128, BE), 256, DQKV_SMEM>>>(x, Wd, Wq, Wk, Wv);
    attn_kernel<<<dim3(NN/64, BE), 256, ATTN_SMEM>>>();
    up_kernel<<<dim3(NN/128, DD/128, BE), 256>>>(Wu, out);
    finalize_kernel<<<1, 256>>>(act, out, out_size);
}